// round 1
// baseline (speedup 1.0000x reference)
#include <cuda_runtime.h>
#include <cstdint>

#define BATCH   2
#define SEQ     2048
#define DMODEL  768
#define NHEADS  12
#define HEADDIM 64
#define KKEEP   614          // int((1-0.7)*2048)
#define TQ      16           // queries per attention block
#define SP      (SEQ + 1)    // padded score row stride (2049)
#define CHUNK   128          // keys per K/V smem chunk

// ---------------- scratch (device globals: no allocations allowed) ----------
__device__ float g_Q[BATCH * NHEADS * SEQ * HEADDIM];
__device__ float g_K[BATCH * NHEADS * SEQ * HEADDIM];
__device__ float g_V[BATCH * NHEADS * SEQ * HEADDIM];
__device__ float g_O[BATCH * SEQ * DMODEL];

// ---------------- QKV projection: C = x @ W^T + b, head-major output --------
__global__ __launch_bounds__(256) void qkv_kernel(
    const float* __restrict__ x,
    const float* __restrict__ Wq, const float* __restrict__ bq,
    const float* __restrict__ Wk, const float* __restrict__ bk,
    const float* __restrict__ Wv, const float* __restrict__ bv)
{
    const float* W; const float* bias; float* dst;
    if (blockIdx.z == 0)      { W = Wq; bias = bq; dst = g_Q; }
    else if (blockIdx.z == 1) { W = Wk; bias = bk; dst = g_K; }
    else                      { W = Wv; bias = bv; dst = g_V; }

    __shared__ float As[8][128];
    __shared__ float Bs[8][128];

    const int tid  = threadIdx.x;
    const int row  = tid >> 1;
    const int col4 = (tid & 1) * 4;
    const int m0   = blockIdx.y * 128;
    const int n0   = blockIdx.x * 128;
    const int ty   = tid >> 4;   // 0..15  (m)
    const int tx   = tid & 15;   // 0..15  (n)

    float acc[8][8];
#pragma unroll
    for (int i = 0; i < 8; ++i)
#pragma unroll
        for (int j = 0; j < 8; ++j) acc[i][j] = 0.f;

    for (int kt = 0; kt < DMODEL; kt += 8) {
        float4 a4 = *(const float4*)(x + (size_t)(m0 + row) * DMODEL + kt + col4);
        float4 b4 = *(const float4*)(W + (size_t)(n0 + row) * DMODEL + kt + col4);
        As[col4 + 0][row] = a4.x; As[col4 + 1][row] = a4.y;
        As[col4 + 2][row] = a4.z; As[col4 + 3][row] = a4.w;
        Bs[col4 + 0][row] = b4.x; Bs[col4 + 1][row] = b4.y;
        Bs[col4 + 2][row] = b4.z; Bs[col4 + 3][row] = b4.w;
        __syncthreads();
#pragma unroll
        for (int k = 0; k < 8; ++k) {
            float ar[8], br[8];
#pragma unroll
            for (int i = 0; i < 8; ++i) ar[i] = As[k][ty * 8 + i];
#pragma unroll
            for (int j = 0; j < 8; ++j) br[j] = Bs[k][tx * 8 + j];
#pragma unroll
            for (int i = 0; i < 8; ++i)
#pragma unroll
                for (int j = 0; j < 8; ++j) acc[i][j] += ar[i] * br[j];
        }
        __syncthreads();
    }

#pragma unroll
    for (int i = 0; i < 8; ++i) {
        int m  = m0 + ty * 8 + i;
        int b_ = m >> 11;          // m / SEQ
        int s_ = m & (SEQ - 1);
#pragma unroll
        for (int j = 0; j < 8; ++j) {
            int n = n0 + tx * 8 + j;
            int h = n >> 6, e = n & 63;
            dst[(((size_t)(b_ * NHEADS + h)) * SEQ + s_) * HEADDIM + e] =
                acc[i][j] + bias[n];
        }
    }
}

// ---------------- Output projection: y = g_O @ Wo^T + bo --------------------
__global__ __launch_bounds__(256) void oproj_kernel(
    const float* __restrict__ Wo, const float* __restrict__ bo,
    float* __restrict__ y)
{
    __shared__ float As[8][128];
    __shared__ float Bs[8][128];

    const int tid  = threadIdx.x;
    const int row  = tid >> 1;
    const int col4 = (tid & 1) * 4;
    const int m0   = blockIdx.y * 128;
    const int n0   = blockIdx.x * 128;
    const int ty   = tid >> 4;
    const int tx   = tid & 15;

    float acc[8][8];
#pragma unroll
    for (int i = 0; i < 8; ++i)
#pragma unroll
        for (int j = 0; j < 8; ++j) acc[i][j] = 0.f;

    for (int kt = 0; kt < DMODEL; kt += 8) {
        float4 a4 = *(const float4*)(g_O + (size_t)(m0 + row) * DMODEL + kt + col4);
        float4 b4 = *(const float4*)(Wo  + (size_t)(n0 + row) * DMODEL + kt + col4);
        As[col4 + 0][row] = a4.x; As[col4 + 1][row] = a4.y;
        As[col4 + 2][row] = a4.z; As[col4 + 3][row] = a4.w;
        Bs[col4 + 0][row] = b4.x; Bs[col4 + 1][row] = b4.y;
        Bs[col4 + 2][row] = b4.z; Bs[col4 + 3][row] = b4.w;
        __syncthreads();
#pragma unroll
        for (int k = 0; k < 8; ++k) {
            float ar[8], br[8];
#pragma unroll
            for (int i = 0; i < 8; ++i) ar[i] = As[k][ty * 8 + i];
#pragma unroll
            for (int j = 0; j < 8; ++j) br[j] = Bs[k][tx * 8 + j];
#pragma unroll
            for (int i = 0; i < 8; ++i)
#pragma unroll
                for (int j = 0; j < 8; ++j) acc[i][j] += ar[i] * br[j];
        }
        __syncthreads();
    }

#pragma unroll
    for (int i = 0; i < 8; ++i) {
        int m = m0 + ty * 8 + i;
#pragma unroll
        for (int j = 0; j < 8; ++j) {
            int n = n0 + tx * 8 + j;
            y[(size_t)m * DMODEL + n] = acc[i][j] + bo[n];
        }
    }
}

// ---------------- attention helpers -----------------------------------------
__device__ __forceinline__ uint32_t f2key(float f) {
    uint32_t u = __float_as_uint(f);
    return (u & 0x80000000u) ? ~u : (u | 0x80000000u);
}

// Warp-cooperative radix-select: exact key of the k-th largest of row[0..SEQ).
__device__ uint32_t warp_kth_key(const float* __restrict__ row, int k,
                                 uint32_t* __restrict__ hist, int lane)
{
    uint32_t prefix = 0, mask_hi = 0;
    int want = k;
#pragma unroll
    for (int pass = 0; pass < 4; ++pass) {
        const int shift = 24 - pass * 8;
        for (int i = lane; i < 256; i += 32) hist[i] = 0;
        __syncwarp();
        for (int i = lane; i < SEQ; i += 32) {
            uint32_t key = f2key(row[i]);
            if (((key ^ prefix) & mask_hi) == 0u)
                atomicAdd(&hist[(key >> shift) & 0xFFu], 1u);
        }
        __syncwarp();
        int c[8]; int lsum = 0;
#pragma unroll
        for (int i = 0; i < 8; ++i) { c[i] = (int)hist[lane * 8 + i]; lsum += c[i]; }
        int incl = lsum;
#pragma unroll
        for (int off = 1; off < 32; off <<= 1) {
            int t = __shfl_up_sync(0xffffffffu, incl, off);
            if (lane >= off) incl += t;
        }
        int total = __shfl_sync(0xffffffffu, incl, 31);
        int run = total - incl;          // count in bins strictly above this lane's bins
        int fd = -1, fw = 0;
#pragma unroll
        for (int i = 7; i >= 0; --i) {
            if (run < want && run + c[i] >= want) { fd = lane * 8 + i; fw = want - run; }
            run += c[i];
        }
        unsigned bal = __ballot_sync(0xffffffffu, fd >= 0);
        int src = __ffs(bal) - 1;
        fd   = __shfl_sync(0xffffffffu, fd, src);
        want = __shfl_sync(0xffffffffu, fw, src);
        prefix  |= (uint32_t)fd << shift;
        mask_hi |= 0xFFu << shift;
        __syncwarp();
    }
    return prefix;
}

// ---------------- attention: scores -> top-k -> softmax -> AV ---------------
__global__ __launch_bounds__(256) void attn_kernel()
{
    extern __shared__ float sc[];                 // [TQ][SP]  (dynamic, 131 KB)
    __shared__ float qs[TQ][HEADDIM];
    __shared__ float kvs[CHUNK][HEADDIM + 1];
    __shared__ uint32_t hist[8][256];
    __shared__ float row_inv[TQ];

    const int tid  = threadIdx.x;
    const int lane = tid & 31, warp = tid >> 5;
    const int ntq  = SEQ / TQ;
    const int qt   = blockIdx.x % ntq;
    const int bh   = blockIdx.x / ntq;

    const float* Qp = g_Q + (size_t)bh * SEQ * HEADDIM;
    const float* Kp = g_K + (size_t)bh * SEQ * HEADDIM;
    const float* Vp = g_V + (size_t)bh * SEQ * HEADDIM;

    for (int idx = tid; idx < TQ * HEADDIM; idx += 256)
        qs[idx >> 6][idx & 63] = Qp[(size_t)(qt * TQ + (idx >> 6)) * HEADDIM + (idx & 63)];

    // ---- phase 1: scores (16 x 2048), chunked GEMM vs K ----
    const int jj = tid & 63;   // key-pair group
    const int qq = tid >> 6;   // query quad group
    for (int c0 = 0; c0 < SEQ; c0 += CHUNK) {
        __syncthreads();
#pragma unroll
        for (int t = 0; t < 8; ++t) {
            int f = tid + t * 256;
            int j = f >> 4, d4 = (f & 15) << 2;
            float4 v = *(const float4*)(Kp + (size_t)(c0 + j) * HEADDIM + d4);
            kvs[j][d4 + 0] = v.x; kvs[j][d4 + 1] = v.y;
            kvs[j][d4 + 2] = v.z; kvs[j][d4 + 3] = v.w;
        }
        __syncthreads();
        float acc[4][2] = {};
        const int j0 = jj * 2;
#pragma unroll 8
        for (int d = 0; d < HEADDIM; ++d) {
            float b0 = kvs[j0][d], b1 = kvs[j0 + 1][d];
#pragma unroll
            for (int i = 0; i < 4; ++i) {
                float a = qs[qq * 4 + i][d];
                acc[i][0] += a * b0;
                acc[i][1] += a * b1;
            }
        }
#pragma unroll
        for (int i = 0; i < 4; ++i) {
            sc[(qq * 4 + i) * SP + c0 + j0]     = acc[i][0] * 0.125f;
            sc[(qq * 4 + i) * SP + c0 + j0 + 1] = acc[i][1] * 0.125f;
        }
    }
    __syncthreads();

    // ---- phase 2: per-row top-k threshold + masked softmax (warp per 2 rows)
    for (int rr = 0; rr < 2; ++rr) {
        int r = warp * 2 + rr;
        float* row = sc + r * SP;
        uint32_t thr = warp_kth_key(row, KKEEP, hist[warp], lane);
        float mx = -3.4e38f;
        for (int i = lane; i < SEQ; i += 32) mx = fmaxf(mx, row[i]);
#pragma unroll
        for (int off = 16; off; off >>= 1)
            mx = fmaxf(mx, __shfl_xor_sync(0xffffffffu, mx, off));
        float sum = 0.f;
        for (int i = lane; i < SEQ; i += 32) {
            float s = row[i];
            float e = (f2key(s) >= thr) ? __expf(s - mx) : 0.f;
            row[i] = e;
            sum += e;
        }
#pragma unroll
        for (int off = 16; off; off >>= 1)
            sum += __shfl_xor_sync(0xffffffffu, sum, off);
        if (lane == 0) row_inv[r] = 1.0f / sum;
    }
    __syncthreads();

    // ---- phase 3: AV = softmax @ V ----
    const int e0 = (tid & 31) * 2;
    const int q0 = (tid >> 5) * 2;
    float acc2[2][2] = {};
    for (int c0 = 0; c0 < SEQ; c0 += CHUNK) {
        __syncthreads();
#pragma unroll
        for (int t = 0; t < 8; ++t) {
            int f = tid + t * 256;
            int j = f >> 4, d4 = (f & 15) << 2;
            float4 v = *(const float4*)(Vp + (size_t)(c0 + j) * HEADDIM + d4);
            kvs[j][d4 + 0] = v.x; kvs[j][d4 + 1] = v.y;
            kvs[j][d4 + 2] = v.z; kvs[j][d4 + 3] = v.w;
        }
        __syncthreads();
#pragma unroll 4
        for (int j = 0; j < CHUNK; ++j) {
            float v0 = kvs[j][e0], v1 = kvs[j][e0 + 1];
            float s0 = sc[q0 * SP + c0 + j];
            float s1 = sc[(q0 + 1) * SP + c0 + j];
            acc2[0][0] += s0 * v0; acc2[0][1] += s0 * v1;
            acc2[1][0] += s1 * v0; acc2[1][1] += s1 * v1;
        }
    }
    const int b_ = bh / NHEADS, h = bh % NHEADS;
#pragma unroll
    for (int i = 0; i < 2; ++i) {
        int s_ = qt * TQ + q0 + i;
        float inv = row_inv[q0 + i];
        size_t base = ((size_t)(b_ * SEQ + s_)) * DMODEL + h * HEADDIM + e0;
        g_O[base]     = acc2[i][0] * inv;
        g_O[base + 1] = acc2[i][1] * inv;
    }
}

// ---------------- launch -----------------------------------------------------
extern "C" void kernel_launch(void* const* d_in, const int* in_sizes, int n_in,
                              void* d_out, int out_size)
{
    const float* x  = (const float*)d_in[0];
    const float* Wq = (const float*)d_in[1];
    const float* bq = (const float*)d_in[2];
    const float* Wk = (const float*)d_in[3];
    const float* bk = (const float*)d_in[4];
    const float* Wv = (const float*)d_in[5];
    const float* bv = (const float*)d_in[6];
    const float* Wo = (const float*)d_in[7];
    const float* bo = (const float*)d_in[8];
    float* y = (float*)d_out;

    dim3 g1(DMODEL / 128, (BATCH * SEQ) / 128, 3);
    qkv_kernel<<<g1, 256>>>(x, Wq, bq, Wk, bk, Wv, bv);

    size_t dyn = (size_t)TQ * SP * sizeof(float);
    cudaFuncSetAttribute(attn_kernel, cudaFuncAttributeMaxDynamicSharedMemorySize, (int)dyn);
    attn_kernel<<<BATCH * NHEADS * (SEQ / TQ), 256, dyn>>>();

    dim3 g2(DMODEL / 128, (BATCH * SEQ) / 128);
    oproj_kernel<<<g2, 256>>>(Wo, bo, y);
}

// round 2
// speedup vs baseline: 1.0019x; 1.0019x over previous
#include <cuda_runtime.h>
#include <cstdint>

#define BATCH   2
#define SEQ     2048
#define DMODEL  768
#define NHEADS  12
#define HEADDIM 64
#define KKEEP   614          // int((1-0.7)*2048)
#define TQ      16           // queries per attention block
#define SP      (SEQ + 1)    // padded score row stride (2049)
#define CHUNK   256          // keys per K/V smem chunk
#define ATHREADS 512

// ---------------- scratch (device globals: no allocations allowed) ----------
__device__ float g_Q[BATCH * NHEADS * SEQ * HEADDIM];
__device__ float g_K[BATCH * NHEADS * SEQ * HEADDIM];
__device__ float g_V[BATCH * NHEADS * SEQ * HEADDIM];
__device__ float g_O[BATCH * SEQ * DMODEL];

// ---------------- QKV projection: C = x @ W^T + b, head-major output --------
__global__ __launch_bounds__(256) void qkv_kernel(
    const float* __restrict__ x,
    const float* __restrict__ Wq, const float* __restrict__ bq,
    const float* __restrict__ Wk, const float* __restrict__ bk,
    const float* __restrict__ Wv, const float* __restrict__ bv)
{
    const float* W; const float* bias; float* dst;
    if (blockIdx.z == 0)      { W = Wq; bias = bq; dst = g_Q; }
    else if (blockIdx.z == 1) { W = Wk; bias = bk; dst = g_K; }
    else                      { W = Wv; bias = bv; dst = g_V; }

    __shared__ float As[8][128];
    __shared__ float Bs[8][128];

    const int tid  = threadIdx.x;
    const int row  = tid >> 1;
    const int col4 = (tid & 1) * 4;
    const int m0   = blockIdx.y * 128;
    const int n0   = blockIdx.x * 128;
    const int ty   = tid >> 4;   // 0..15  (m)
    const int tx   = tid & 15;   // 0..15  (n)

    float acc[8][8];
#pragma unroll
    for (int i = 0; i < 8; ++i)
#pragma unroll
        for (int j = 0; j < 8; ++j) acc[i][j] = 0.f;

    for (int kt = 0; kt < DMODEL; kt += 8) {
        float4 a4 = *(const float4*)(x + (size_t)(m0 + row) * DMODEL + kt + col4);
        float4 b4 = *(const float4*)(W + (size_t)(n0 + row) * DMODEL + kt + col4);
        As[col4 + 0][row] = a4.x; As[col4 + 1][row] = a4.y;
        As[col4 + 2][row] = a4.z; As[col4 + 3][row] = a4.w;
        Bs[col4 + 0][row] = b4.x; Bs[col4 + 1][row] = b4.y;
        Bs[col4 + 2][row] = b4.z; Bs[col4 + 3][row] = b4.w;
        __syncthreads();
#pragma unroll
        for (int k = 0; k < 8; ++k) {
            float ar[8], br[8];
#pragma unroll
            for (int i = 0; i < 8; ++i) ar[i] = As[k][ty * 8 + i];
#pragma unroll
            for (int j = 0; j < 8; ++j) br[j] = Bs[k][tx * 8 + j];
#pragma unroll
            for (int i = 0; i < 8; ++i)
#pragma unroll
                for (int j = 0; j < 8; ++j) acc[i][j] += ar[i] * br[j];
        }
        __syncthreads();
    }

#pragma unroll
    for (int i = 0; i < 8; ++i) {
        int m  = m0 + ty * 8 + i;
        int b_ = m >> 11;          // m / SEQ
        int s_ = m & (SEQ - 1);
#pragma unroll
        for (int j = 0; j < 8; ++j) {
            int n = n0 + tx * 8 + j;
            int h = n >> 6, e = n & 63;
            dst[(((size_t)(b_ * NHEADS + h)) * SEQ + s_) * HEADDIM + e] =
                acc[i][j] + bias[n];
        }
    }
}

// ---------------- Output projection: y = g_O @ Wo^T + bo --------------------
__global__ __launch_bounds__(256) void oproj_kernel(
    const float* __restrict__ Wo, const float* __restrict__ bo,
    float* __restrict__ y)
{
    __shared__ float As[8][128];
    __shared__ float Bs[8][128];

    const int tid  = threadIdx.x;
    const int row  = tid >> 1;
    const int col4 = (tid & 1) * 4;
    const int m0   = blockIdx.y * 128;
    const int n0   = blockIdx.x * 128;
    const int ty   = tid >> 4;
    const int tx   = tid & 15;

    float acc[8][8];
#pragma unroll
    for (int i = 0; i < 8; ++i)
#pragma unroll
        for (int j = 0; j < 8; ++j) acc[i][j] = 0.f;

    for (int kt = 0; kt < DMODEL; kt += 8) {
        float4 a4 = *(const float4*)(g_O + (size_t)(m0 + row) * DMODEL + kt + col4);
        float4 b4 = *(const float4*)(Wo  + (size_t)(n0 + row) * DMODEL + kt + col4);
        As[col4 + 0][row] = a4.x; As[col4 + 1][row] = a4.y;
        As[col4 + 2][row] = a4.z; As[col4 + 3][row] = a4.w;
        Bs[col4 + 0][row] = b4.x; Bs[col4 + 1][row] = b4.y;
        Bs[col4 + 2][row] = b4.z; Bs[col4 + 3][row] = b4.w;
        __syncthreads();
#pragma unroll
        for (int k = 0; k < 8; ++k) {
            float ar[8], br[8];
#pragma unroll
            for (int i = 0; i < 8; ++i) ar[i] = As[k][ty * 8 + i];
#pragma unroll
            for (int j = 0; j < 8; ++j) br[j] = Bs[k][tx * 8 + j];
#pragma unroll
            for (int i = 0; i < 8; ++i)
#pragma unroll
                for (int j = 0; j < 8; ++j) acc[i][j] += ar[i] * br[j];
        }
        __syncthreads();
    }

#pragma unroll
    for (int i = 0; i < 8; ++i) {
        int m = m0 + ty * 8 + i;
#pragma unroll
        for (int j = 0; j < 8; ++j) {
            int n = n0 + tx * 8 + j;
            y[(size_t)m * DMODEL + n] = acc[i][j] + bo[n];
        }
    }
}

// ---------------- attention helpers -----------------------------------------
__device__ __forceinline__ uint32_t f2key(float f) {
    uint32_t u = __float_as_uint(f);
    return (u & 0x80000000u) ? ~u : (u | 0x80000000u);
}

// Warp-cooperative radix-select: exact key of the k-th largest of row[0..SEQ).
__device__ uint32_t warp_kth_key(const float* __restrict__ row, int k,
                                 uint32_t* __restrict__ hist, int lane)
{
    uint32_t prefix = 0, mask_hi = 0;
    int want = k;
#pragma unroll
    for (int pass = 0; pass < 4; ++pass) {
        const int shift = 24 - pass * 8;
        for (int i = lane; i < 256; i += 32) hist[i] = 0;
        __syncwarp();
        for (int i = lane; i < SEQ; i += 32) {
            uint32_t key = f2key(row[i]);
            if (((key ^ prefix) & mask_hi) == 0u)
                atomicAdd(&hist[(key >> shift) & 0xFFu], 1u);
        }
        __syncwarp();
        int c[8]; int lsum = 0;
#pragma unroll
        for (int i = 0; i < 8; ++i) { c[i] = (int)hist[lane * 8 + i]; lsum += c[i]; }
        int incl = lsum;
#pragma unroll
        for (int off = 1; off < 32; off <<= 1) {
            int t = __shfl_up_sync(0xffffffffu, incl, off);
            if (lane >= off) incl += t;
        }
        int total = __shfl_sync(0xffffffffu, incl, 31);
        int run = total - incl;          // count in bins strictly above this lane's bins
        int fd = -1, fw = 0;
#pragma unroll
        for (int i = 7; i >= 0; --i) {
            if (run < want && run + c[i] >= want) { fd = lane * 8 + i; fw = want - run; }
            run += c[i];
        }
        unsigned bal = __ballot_sync(0xffffffffu, fd >= 0);
        int src = __ffs(bal) - 1;
        fd   = __shfl_sync(0xffffffffu, fd, src);
        want = __shfl_sync(0xffffffffu, fw, src);
        prefix  |= (uint32_t)fd << shift;
        mask_hi |= 0xFFu << shift;
        __syncwarp();
    }
    return prefix;
}

// ---------------- attention: scores -> top-k -> softmax -> AV ---------------
// dynamic smem layout: sc[TQ][SP] then kvs[CHUNK][65]
__global__ __launch_bounds__(ATHREADS) void attn_kernel()
{
    extern __shared__ float dynsm[];
    float* sc = dynsm;                                  // [TQ][SP]
    float (*kvs)[65] = (float(*)[65])(dynsm + TQ * SP); // [CHUNK][65]
    __shared__ float qs[TQ][HEADDIM];
    __shared__ uint32_t hist[16][256];
    __shared__ float row_inv[TQ];

    const int tid  = threadIdx.x;
    const int lane = tid & 31, warp = tid >> 5;
    const int ntq  = SEQ / TQ;
    const int qt   = blockIdx.x % ntq;
    const int bh   = blockIdx.x / ntq;

    const float* Qp = g_Q + (size_t)bh * SEQ * HEADDIM;
    const float* Kp = g_K + (size_t)bh * SEQ * HEADDIM;
    const float* Vp = g_V + (size_t)bh * SEQ * HEADDIM;

    for (int idx = tid; idx < TQ * HEADDIM; idx += ATHREADS)
        qs[idx >> 6][idx & 63] = Qp[(size_t)(qt * TQ + (idx >> 6)) * HEADDIM + (idx & 63)];

    // ---- phase 1: scores (16 x 2048) ----
    // 4q x 4k micro-tile, k strided by 64 (conflict-free), d split 2-way interleaved
    const int dpart = tid & 1;
    const int tile  = tid >> 1;        // 0..255
    const int qg    = tile >> 6;       // 0..3
    const int kg    = tile & 63;       // 0..63
    const int q0    = qg * 4;

    for (int c0 = 0; c0 < SEQ; c0 += CHUNK) {
        __syncthreads();
#pragma unroll
        for (int t = 0; t < 8; ++t) {
            int f = tid + t * ATHREADS;
            int j = f >> 4, d4 = (f & 15) << 2;
            float4 v = *(const float4*)(Kp + (size_t)(c0 + j) * HEADDIM + d4);
            kvs[j][d4 + 0] = v.x; kvs[j][d4 + 1] = v.y;
            kvs[j][d4 + 2] = v.z; kvs[j][d4 + 3] = v.w;
        }
        __syncthreads();
        float acc[4][4] = {};
#pragma unroll 8
        for (int it = 0; it < 32; ++it) {
            int d = (it << 1) | dpart;
            float a0 = qs[q0 + 0][d], a1 = qs[q0 + 1][d];
            float a2 = qs[q0 + 2][d], a3 = qs[q0 + 3][d];
            float b0 = kvs[kg][d],       b1 = kvs[kg + 64][d];
            float b2 = kvs[kg + 128][d], b3 = kvs[kg + 192][d];
            acc[0][0] += a0 * b0; acc[0][1] += a0 * b1; acc[0][2] += a0 * b2; acc[0][3] += a0 * b3;
            acc[1][0] += a1 * b0; acc[1][1] += a1 * b1; acc[1][2] += a1 * b2; acc[1][3] += a1 * b3;
            acc[2][0] += a2 * b0; acc[2][1] += a2 * b1; acc[2][2] += a2 * b2; acc[2][3] += a2 * b3;
            acc[3][0] += a3 * b0; acc[3][1] += a3 * b1; acc[3][2] += a3 * b2; acc[3][3] += a3 * b3;
        }
#pragma unroll
        for (int i = 0; i < 4; ++i)
#pragma unroll
            for (int j = 0; j < 4; ++j) {
                float v = acc[i][j] + __shfl_xor_sync(0xffffffffu, acc[i][j], 1);
                if (dpart == 0)
                    sc[(q0 + i) * SP + c0 + kg + j * 64] = v * 0.125f;
            }
    }
    __syncthreads();

    // ---- phase 2: per-row top-k threshold + masked softmax (warp per row) --
    {
        int r = warp;                      // 16 warps, 16 rows
        float* row = sc + r * SP;
        uint32_t thr = warp_kth_key(row, KKEEP, hist[warp], lane);
        float mx = -3.4e38f;
        for (int i = lane; i < SEQ; i += 32) mx = fmaxf(mx, row[i]);
#pragma unroll
        for (int off = 16; off; off >>= 1)
            mx = fmaxf(mx, __shfl_xor_sync(0xffffffffu, mx, off));
        float sum = 0.f;
        for (int i = lane; i < SEQ; i += 32) {
            float s = row[i];
            float e = (f2key(s) >= thr) ? __expf(s - mx) : 0.f;
            row[i] = e;
            sum += e;
        }
#pragma unroll
        for (int off = 16; off; off >>= 1)
            sum += __shfl_xor_sync(0xffffffffu, sum, off);
        if (lane == 0) row_inv[r] = 1.0f / sum;
    }
    __syncthreads();

    // ---- phase 3: AV = softmax @ V ----
    // 4q x 4e micro-tile, e strided by 16, j split 8-way interleaved
    const int jp  = tid & 7;
    const int t3  = tid >> 3;          // 0..63
    const int eg  = t3 & 15;           // 0..15
    const int q30 = (t3 >> 4) * 4;     // 0,4,8,12
    float a3[4][4] = {};
    for (int c0 = 0; c0 < SEQ; c0 += CHUNK) {
        __syncthreads();
#pragma unroll
        for (int t = 0; t < 8; ++t) {
            int f = tid + t * ATHREADS;
            int j = f >> 4, d4 = (f & 15) << 2;
            float4 v = *(const float4*)(Vp + (size_t)(c0 + j) * HEADDIM + d4);
            kvs[j][d4 + 0] = v.x; kvs[j][d4 + 1] = v.y;
            kvs[j][d4 + 2] = v.z; kvs[j][d4 + 3] = v.w;
        }
        __syncthreads();
#pragma unroll 4
        for (int jj = jp; jj < CHUNK; jj += 8) {
            float s0 = sc[(q30 + 0) * SP + c0 + jj];
            float s1 = sc[(q30 + 1) * SP + c0 + jj];
            float s2 = sc[(q30 + 2) * SP + c0 + jj];
            float s3 = sc[(q30 + 3) * SP + c0 + jj];
            float v0 = kvs[jj][eg],      v1 = kvs[jj][eg + 16];
            float v2 = kvs[jj][eg + 32], v3 = kvs[jj][eg + 48];
            a3[0][0] += s0 * v0; a3[0][1] += s0 * v1; a3[0][2] += s0 * v2; a3[0][3] += s0 * v3;
            a3[1][0] += s1 * v0; a3[1][1] += s1 * v1; a3[1][2] += s1 * v2; a3[1][3] += s1 * v3;
            a3[2][0] += s2 * v0; a3[2][1] += s2 * v1; a3[2][2] += s2 * v2; a3[2][3] += s2 * v3;
            a3[3][0] += s3 * v0; a3[3][1] += s3 * v1; a3[3][2] += s3 * v2; a3[3][3] += s3 * v3;
        }
    }
#pragma unroll
    for (int i = 0; i < 4; ++i)
#pragma unroll
        for (int jv = 0; jv < 4; ++jv) {
            a3[i][jv] += __shfl_xor_sync(0xffffffffu, a3[i][jv], 1);
            a3[i][jv] += __shfl_xor_sync(0xffffffffu, a3[i][jv], 2);
            a3[i][jv] += __shfl_xor_sync(0xffffffffu, a3[i][jv], 4);
        }
    if (jp == 0) {
        const int b_ = bh / NHEADS, h = bh % NHEADS;
#pragma unroll
        for (int i = 0; i < 4; ++i) {
            int s_ = qt * TQ + q30 + i;
            float inv = row_inv[q30 + i];
            size_t base = ((size_t)(b_ * SEQ + s_)) * DMODEL + h * HEADDIM;
#pragma unroll
            for (int jv = 0; jv < 4; ++jv)
                g_O[base + eg + 16 * jv] = a3[i][jv] * inv;
        }
    }
}

// ---------------- launch -----------------------------------------------------
extern "C" void kernel_launch(void* const* d_in, const int* in_sizes, int n_in,
                              void* d_out, int out_size)
{
    const float* x  = (const float*)d_in[0];
    const float* Wq = (const float*)d_in[1];
    const float* bq = (const float*)d_in[2];
    const float* Wk = (const float*)d_in[3];
    const float* bk = (const float*)d_in[4];
    const float* Wv = (const float*)d_in[5];
    const float* bv = (const float*)d_in[6];
    const float* Wo = (const float*)d_in[7];
    const float* bo = (const float*)d_in[8];
    float* y = (float*)d_out;

    dim3 g1(DMODEL / 128, (BATCH * SEQ) / 128, 3);
    qkv_kernel<<<g1, 256>>>(x, Wq, bq, Wk, bk, Wv, bv);

    size_t dyn = (size_t)TQ * SP * sizeof(float) + (size_t)CHUNK * 65 * sizeof(float);
    cudaFuncSetAttribute(attn_kernel, cudaFuncAttributeMaxDynamicSharedMemorySize, (int)dyn);
    attn_kernel<<<BATCH * NHEADS * (SEQ / TQ), ATHREADS, dyn>>>();

    dim3 g2(DMODEL / 128, (BATCH * SEQ) / 128);
    oproj_kernel<<<g2, 256>>>(Wo, bo, y);
}

// round 3
// speedup vs baseline: 1.2717x; 1.2693x over previous
#include <cuda_runtime.h>
#include <cstdint>

#define BATCH   2
#define SEQ     2048
#define DMODEL  768
#define NHEADS  12
#define HEADDIM 64
#define KKEEP   614          // int((1-0.7)*2048)
#define TQ      128          // queries per attention CTA
#define ATHREADS 512
#define NQT     (SEQ / TQ)   // 16 query tiles per head

// ---------------- scratch (device globals: no allocations allowed) ----------
__device__ float g_Q[BATCH * NHEADS * SEQ * HEADDIM];
__device__ float g_K[BATCH * NHEADS * SEQ * HEADDIM];
__device__ float g_V[BATCH * NHEADS * SEQ * HEADDIM];
__device__ float g_O[BATCH * SEQ * DMODEL];
__device__ float g_S[(size_t)BATCH * NHEADS * SEQ * SEQ];   // 403 MB scores/probs

// dynamic smem: 36864 floats = 147456 B (union across phases)
#define DYN_FLOATS 36864

// ---------------- QKV projection: C = x @ W^T + b, head-major output --------
__global__ __launch_bounds__(256) void qkv_kernel(
    const float* __restrict__ x,
    const float* __restrict__ Wq, const float* __restrict__ bq,
    const float* __restrict__ Wk, const float* __restrict__ bk,
    const float* __restrict__ Wv, const float* __restrict__ bv)
{
    const float* W; const float* bias; float* dst;
    if (blockIdx.z == 0)      { W = Wq; bias = bq; dst = g_Q; }
    else if (blockIdx.z == 1) { W = Wk; bias = bk; dst = g_K; }
    else                      { W = Wv; bias = bv; dst = g_V; }

    __shared__ float As[8][128];
    __shared__ float Bs[8][128];

    const int tid  = threadIdx.x;
    const int row  = tid >> 1;
    const int col4 = (tid & 1) * 4;
    const int m0   = blockIdx.y * 128;
    const int n0   = blockIdx.x * 128;
    const int ty   = tid >> 4;
    const int tx   = tid & 15;

    float acc[8][8];
#pragma unroll
    for (int i = 0; i < 8; ++i)
#pragma unroll
        for (int j = 0; j < 8; ++j) acc[i][j] = 0.f;

    for (int kt = 0; kt < DMODEL; kt += 8) {
        float4 a4 = *(const float4*)(x + (size_t)(m0 + row) * DMODEL + kt + col4);
        float4 b4 = *(const float4*)(W + (size_t)(n0 + row) * DMODEL + kt + col4);
        As[col4 + 0][row] = a4.x; As[col4 + 1][row] = a4.y;
        As[col4 + 2][row] = a4.z; As[col4 + 3][row] = a4.w;
        Bs[col4 + 0][row] = b4.x; Bs[col4 + 1][row] = b4.y;
        Bs[col4 + 2][row] = b4.z; Bs[col4 + 3][row] = b4.w;
        __syncthreads();
#pragma unroll
        for (int k = 0; k < 8; ++k) {
            float ar[8], br[8];
#pragma unroll
            for (int i = 0; i < 8; ++i) ar[i] = As[k][ty * 8 + i];
#pragma unroll
            for (int j = 0; j < 8; ++j) br[j] = Bs[k][tx * 8 + j];
#pragma unroll
            for (int i = 0; i < 8; ++i)
#pragma unroll
                for (int j = 0; j < 8; ++j) acc[i][j] += ar[i] * br[j];
        }
        __syncthreads();
    }

#pragma unroll
    for (int i = 0; i < 8; ++i) {
        int m  = m0 + ty * 8 + i;
        int b_ = m >> 11;
        int s_ = m & (SEQ - 1);
#pragma unroll
        for (int j = 0; j < 8; ++j) {
            int n = n0 + tx * 8 + j;
            int h = n >> 6, e = n & 63;
            dst[(((size_t)(b_ * NHEADS + h)) * SEQ + s_) * HEADDIM + e] =
                acc[i][j] + bias[n];
        }
    }
}

// ---------------- Output projection: y = g_O @ Wo^T + bo --------------------
__global__ __launch_bounds__(256) void oproj_kernel(
    const float* __restrict__ Wo, const float* __restrict__ bo,
    float* __restrict__ y)
{
    __shared__ float As[8][128];
    __shared__ float Bs[8][128];

    const int tid  = threadIdx.x;
    const int row  = tid >> 1;
    const int col4 = (tid & 1) * 4;
    const int m0   = blockIdx.y * 128;
    const int n0   = blockIdx.x * 128;
    const int ty   = tid >> 4;
    const int tx   = tid & 15;

    float acc[8][8];
#pragma unroll
    for (int i = 0; i < 8; ++i)
#pragma unroll
        for (int j = 0; j < 8; ++j) acc[i][j] = 0.f;

    for (int kt = 0; kt < DMODEL; kt += 8) {
        float4 a4 = *(const float4*)(g_O + (size_t)(m0 + row) * DMODEL + kt + col4);
        float4 b4 = *(const float4*)(Wo  + (size_t)(n0 + row) * DMODEL + kt + col4);
        As[col4 + 0][row] = a4.x; As[col4 + 1][row] = a4.y;
        As[col4 + 2][row] = a4.z; As[col4 + 3][row] = a4.w;
        Bs[col4 + 0][row] = b4.x; Bs[col4 + 1][row] = b4.y;
        Bs[col4 + 2][row] = b4.z; Bs[col4 + 3][row] = b4.w;
        __syncthreads();
#pragma unroll
        for (int k = 0; k < 8; ++k) {
            float ar[8], br[8];
#pragma unroll
            for (int i = 0; i < 8; ++i) ar[i] = As[k][ty * 8 + i];
#pragma unroll
            for (int j = 0; j < 8; ++j) br[j] = Bs[k][tx * 8 + j];
#pragma unroll
            for (int i = 0; i < 8; ++i)
#pragma unroll
                for (int j = 0; j < 8; ++j) acc[i][j] += ar[i] * br[j];
        }
        __syncthreads();
    }

#pragma unroll
    for (int i = 0; i < 8; ++i) {
        int m = m0 + ty * 8 + i;
#pragma unroll
        for (int j = 0; j < 8; ++j) {
            int n = n0 + tx * 8 + j;
            y[(size_t)m * DMODEL + n] = acc[i][j] + bo[n];
        }
    }
}

// ---------------- attention helpers -----------------------------------------
__device__ __forceinline__ uint32_t f2key(float f) {
    uint32_t u = __float_as_uint(f);
    return (u & 0x80000000u) ? ~u : (u | 0x80000000u);
}

// Warp radix-select (exact k-th largest key) with match-aggregated atomics.
__device__ uint32_t warp_kth_key(const float* __restrict__ row, int k,
                                 uint32_t* __restrict__ hist, int lane)
{
    uint32_t prefix = 0, mask_hi = 0;
    int want = k;
#pragma unroll
    for (int pass = 0; pass < 4; ++pass) {
        const int shift = 24 - pass * 8;
        for (int i = lane; i < 256; i += 32) hist[i] = 0;
        __syncwarp();
        for (int i = lane; i < SEQ; i += 32) {
            uint32_t key = f2key(row[i]);
            bool act = (((key ^ prefix) & mask_hi) == 0u);
            unsigned bal = __ballot_sync(0xffffffffu, act);
            if (act) {
                int bin = (key >> shift) & 0xFF;
                unsigned peers = __match_any_sync(bal, bin);
                if ((int)__ffs(peers) - 1 == lane)
                    atomicAdd(&hist[bin], (uint32_t)__popc(peers));
            }
        }
        __syncwarp();
        int c[8]; int lsum = 0;
#pragma unroll
        for (int i = 0; i < 8; ++i) { c[i] = (int)hist[lane * 8 + i]; lsum += c[i]; }
        int incl = lsum;
#pragma unroll
        for (int off = 1; off < 32; off <<= 1) {
            int t = __shfl_up_sync(0xffffffffu, incl, off);
            if (lane >= off) incl += t;
        }
        int total = __shfl_sync(0xffffffffu, incl, 31);
        int run = total - incl;
        int fd = -1, fw = 0;
#pragma unroll
        for (int i = 7; i >= 0; --i) {
            if (run < want && run + c[i] >= want) { fd = lane * 8 + i; fw = want - run; }
            run += c[i];
        }
        unsigned bal2 = __ballot_sync(0xffffffffu, fd >= 0);
        int src = __ffs(bal2) - 1;
        fd   = __shfl_sync(0xffffffffu, fd, src);
        want = __shfl_sync(0xffffffffu, fw, src);
        prefix  |= (uint32_t)fd << shift;
        mask_hi |= 0xFFu << shift;
        __syncwarp();
    }
    return prefix;
}

// ---------------- attention: one CTA = 128 query rows of one head -----------
__global__ __launch_bounds__(ATHREADS) void attn_kernel()
{
    extern __shared__ float sm[];

    const int tid  = threadIdx.x;
    const int lane = tid & 31, warp = tid >> 5;
    const int qt   = blockIdx.x & (NQT - 1);
    const int bh   = blockIdx.x >> 4;              // NQT == 16
    const int qrow0 = qt * TQ;

    const float* Qp = g_Q + (size_t)bh * SEQ * HEADDIM;
    const float* Kp = g_K + (size_t)bh * SEQ * HEADDIM;
    const float* Vp = g_V + (size_t)bh * SEQ * HEADDIM;
    float* Sp = g_S + (size_t)blockIdx.x * TQ * SEQ;   // [128][2048]

    // ================= phase 1: scores = Q @ K^T * scale ====================
    {
        float* Qt = sm;                  // [64][132]  (transposed Q)
        float* Ks = sm + 64 * 132;       // [128][65]

        // fill Qt (once)
        for (int it = 0; it < 16; ++it) {
            int idx = tid + it * ATHREADS;          // 8192
            int q = idx >> 6, d = idx & 63;
            Qt[d * 132 + q] = Qp[(size_t)(qrow0 + q) * HEADDIM + d];
        }

        const int kg = tid & 31;
        const int q0 = (tid >> 5) * 8;

        for (int c0 = 0; c0 < SEQ; c0 += 128) {
            __syncthreads();
            for (int it = 0; it < 16; ++it) {
                int idx = tid + it * ATHREADS;       // 8192
                int k = idx >> 6, d = idx & 63;
                Ks[k * 65 + d] = Kp[(size_t)(c0 + k) * HEADDIM + d];
            }
            __syncthreads();

            float acc[8][4];
#pragma unroll
            for (int i = 0; i < 8; ++i)
#pragma unroll
                for (int j = 0; j < 4; ++j) acc[i][j] = 0.f;

#pragma unroll 8
            for (int d = 0; d < HEADDIM; ++d) {
                float4 a0 = *(const float4*)&Qt[d * 132 + q0];
                float4 a1 = *(const float4*)&Qt[d * 132 + q0 + 4];
                float b0 = Ks[kg * 65 + d];
                float b1 = Ks[(kg + 32) * 65 + d];
                float b2 = Ks[(kg + 64) * 65 + d];
                float b3 = Ks[(kg + 96) * 65 + d];
                float a[8] = {a0.x, a0.y, a0.z, a0.w, a1.x, a1.y, a1.z, a1.w};
#pragma unroll
                for (int i = 0; i < 8; ++i) {
                    acc[i][0] += a[i] * b0;
                    acc[i][1] += a[i] * b1;
                    acc[i][2] += a[i] * b2;
                    acc[i][3] += a[i] * b3;
                }
            }
#pragma unroll
            for (int i = 0; i < 8; ++i)
#pragma unroll
                for (int j = 0; j < 4; ++j)
                    Sp[(size_t)(q0 + i) * SEQ + c0 + kg + 32 * j] = acc[i][j] * 0.125f;
        }
        __syncthreads();
    }

    // ================= phase 2: top-k threshold + softmax (normalized) ======
    {
        float* rowbuf = sm + warp * SEQ;                       // 8 KB per warp
        uint32_t* hist = (uint32_t*)(sm + 16 * SEQ) + warp * 256;

        for (int t = 0; t < 8; ++t) {
            int r = warp * 8 + t;
            float* grow = Sp + (size_t)r * SEQ;
            float mx = -3.4e38f;
            for (int it = 0; it < 16; ++it) {
                float4 v = ((const float4*)grow)[lane + it * 32];
                ((float4*)rowbuf)[lane + it * 32] = v;
                mx = fmaxf(mx, fmaxf(fmaxf(v.x, v.y), fmaxf(v.z, v.w)));
            }
#pragma unroll
            for (int off = 16; off; off >>= 1)
                mx = fmaxf(mx, __shfl_xor_sync(0xffffffffu, mx, off));
            __syncwarp();

            uint32_t thr = warp_kth_key(rowbuf, KKEEP, hist, lane);

            float sum = 0.f;
            for (int i = lane; i < SEQ; i += 32) {
                float s = rowbuf[i];
                float e = (f2key(s) >= thr) ? __expf(s - mx) : 0.f;
                rowbuf[i] = e;
                sum += e;
            }
#pragma unroll
            for (int off = 16; off; off >>= 1)
                sum += __shfl_xor_sync(0xffffffffu, sum, off);
            float inv = 1.0f / sum;
            __syncwarp();
            for (int it = 0; it < 16; ++it) {
                float4 e4 = ((const float4*)rowbuf)[lane + it * 32];
                e4.x *= inv; e4.y *= inv; e4.z *= inv; e4.w *= inv;
                ((float4*)grow)[lane + it * 32] = e4;
            }
            __syncwarp();
        }
    }

    // ================= phase 3: out = probs @ V ============================
    {
        float* At = sm;                  // [128 j][129]  (transposed probs)
        float* Vs = sm + 128 * 129;      // [128 j][68]

        const int jp  = tid & 3;
        const int grp = tid >> 2;                // 0..127
        const int e0  = (grp & 7) * 8;
        const int q0  = (grp >> 3) * 8;          // == warp * 8

        float acc[8][8];
#pragma unroll
        for (int i = 0; i < 8; ++i)
#pragma unroll
            for (int j = 0; j < 8; ++j) acc[i][j] = 0.f;

        for (int c0 = 0; c0 < SEQ; c0 += 128) {
            __syncthreads();
            for (int it = 0; it < 32; ++it) {
                int idx = tid + it * ATHREADS;        // 16384
                int q = idx >> 7, j = idx & 127;
                At[j * 129 + q] = Sp[(size_t)q * SEQ + c0 + j];
            }
            for (int it = 0; it < 4; ++it) {
                int idx4 = tid + it * ATHREADS;       // 2048 float4s
                int j = idx4 >> 4, d4 = (idx4 & 15) << 2;
                float4 v = *(const float4*)(Vp + (size_t)(c0 + j) * HEADDIM + d4);
                *(float4*)&Vs[j * 68 + d4] = v;
            }
            __syncthreads();

#pragma unroll 4
            for (int jj = 0; jj < 32; ++jj) {
                int j = jj * 4 + jp;
                float a[8];
#pragma unroll
                for (int i = 0; i < 8; ++i) a[i] = At[j * 129 + q0 + i];
                float4 v0 = *(const float4*)&Vs[j * 68 + e0];
                float4 v1 = *(const float4*)&Vs[j * 68 + e0 + 4];
                float v[8] = {v0.x, v0.y, v0.z, v0.w, v1.x, v1.y, v1.z, v1.w};
#pragma unroll
                for (int i = 0; i < 8; ++i)
#pragma unroll
                    for (int j2 = 0; j2 < 8; ++j2)
                        acc[i][j2] += a[i] * v[j2];
            }
        }

#pragma unroll
        for (int i = 0; i < 8; ++i)
#pragma unroll
            for (int j2 = 0; j2 < 8; ++j2) {
                acc[i][j2] += __shfl_xor_sync(0xffffffffu, acc[i][j2], 1);
                acc[i][j2] += __shfl_xor_sync(0xffffffffu, acc[i][j2], 2);
            }

        if (jp == 0) {
            const int b_ = bh / NHEADS, h = bh % NHEADS;
#pragma unroll
            for (int i = 0; i < 8; ++i) {
                int s_ = qrow0 + q0 + i;
                size_t base = ((size_t)(b_ * SEQ + s_)) * DMODEL + h * HEADDIM + e0;
                float4 o0 = {acc[i][0], acc[i][1], acc[i][2], acc[i][3]};
                float4 o1 = {acc[i][4], acc[i][5], acc[i][6], acc[i][7]};
                *(float4*)&g_O[base]     = o0;
                *(float4*)&g_O[base + 4] = o1;
            }
        }
    }
}

// ---------------- launch -----------------------------------------------------
extern "C" void kernel_launch(void* const* d_in, const int* in_sizes, int n_in,
                              void* d_out, int out_size)
{
    const float* x  = (const float*)d_in[0];
    const float* Wq = (const float*)d_in[1];
    const float* bq = (const float*)d_in[2];
    const float* Wk = (const float*)d_in[3];
    const float* bk = (const float*)d_in[4];
    const float* Wv = (const float*)d_in[5];
    const float* bv = (const float*)d_in[6];
    const float* Wo = (const float*)d_in[7];
    const float* bo = (const float*)d_in[8];
    float* y = (float*)d_out;

    dim3 g1(DMODEL / 128, (BATCH * SEQ) / 128, 3);
    qkv_kernel<<<g1, 256>>>(x, Wq, bq, Wk, bk, Wv, bv);

    size_t dyn = (size_t)DYN_FLOATS * sizeof(float);     // 147456 B
    cudaFuncSetAttribute(attn_kernel, cudaFuncAttributeMaxDynamicSharedMemorySize, (int)dyn);
    attn_kernel<<<BATCH * NHEADS * NQT, ATHREADS, dyn>>>();

    dim3 g2(DMODEL / 128, (BATCH * SEQ) / 128);
    oproj_kernel<<<g2, 256>>>(Wo, bo, y);
}

// round 5
// speedup vs baseline: 1.4221x; 1.1182x over previous
#include <cuda_runtime.h>
#include <cuda_bf16.h>
#include <cstdint>

#define BATCH   2
#define SEQ     2048
#define DMODEL  768
#define NHEADS  12
#define HEADDIM 64
#define KKEEP   614
#define TQ      128
#define NQT     (SEQ / TQ)
#define ATHREADS 512

// ---------------- device scratch --------------------------------------------
__device__ __nv_bfloat16 g_Qh[BATCH * NHEADS * SEQ * HEADDIM];
__device__ __nv_bfloat16 g_Ql[BATCH * NHEADS * SEQ * HEADDIM];
__device__ __nv_bfloat16 g_Kh[BATCH * NHEADS * SEQ * HEADDIM];
__device__ __nv_bfloat16 g_Kl[BATCH * NHEADS * SEQ * HEADDIM];
__device__ __nv_bfloat16 g_Vth[BATCH * NHEADS * HEADDIM * SEQ];  // [bh][e][s]
__device__ __nv_bfloat16 g_Vtl[BATCH * NHEADS * HEADDIM * SEQ];
__device__ float g_O[BATCH * SEQ * DMODEL];
__device__ float g_S[(size_t)BATCH * NHEADS * SEQ * SEQ];

// m16n8k16 bf16 mma, fp32 accum (arch-neutral PTX, runs as HMMA on sm_103)
#define MMA16816(c, a, b)                                                        \
    asm volatile("mma.sync.aligned.m16n8k16.row.col.f32.bf16.bf16.f32 "          \
        "{%0,%1,%2,%3}, {%4,%5,%6,%7}, {%8,%9}, {%0,%1,%2,%3};"                  \
        : "+f"((c)[0]), "+f"((c)[1]), "+f"((c)[2]), "+f"((c)[3])                 \
        : "r"((a)[0]), "r"((a)[1]), "r"((a)[2]), "r"((a)[3]),                    \
          "r"((b)[0]), "r"((b)[1]))

// ---------------- QKV projection (fp32 GEMM, bf16 hi/lo epilogue) ------------
__global__ __launch_bounds__(256) void qkv_kernel(
    const float* __restrict__ x,
    const float* __restrict__ Wq, const float* __restrict__ bq,
    const float* __restrict__ Wk, const float* __restrict__ bk,
    const float* __restrict__ Wv, const float* __restrict__ bv)
{
    const float* W; const float* bias;
    __nv_bfloat16 *dh, *dl;
    const int z = blockIdx.z;
    if (z == 0)      { W = Wq; bias = bq; dh = g_Qh;  dl = g_Ql;  }
    else if (z == 1) { W = Wk; bias = bk; dh = g_Kh;  dl = g_Kl;  }
    else             { W = Wv; bias = bv; dh = g_Vth; dl = g_Vtl; }

    __shared__ float As[8][128];
    __shared__ float Bs[8][128];

    const int tid  = threadIdx.x;
    const int row  = tid >> 1;
    const int col4 = (tid & 1) * 4;
    const int m0   = blockIdx.y * 128;
    const int n0   = blockIdx.x * 128;
    const int ty   = tid >> 4;
    const int tx   = tid & 15;

    float acc[8][8];
#pragma unroll
    for (int i = 0; i < 8; ++i)
#pragma unroll
        for (int j = 0; j < 8; ++j) acc[i][j] = 0.f;

    for (int kt = 0; kt < DMODEL; kt += 8) {
        float4 a4 = *(const float4*)(x + (size_t)(m0 + row) * DMODEL + kt + col4);
        float4 b4 = *(const float4*)(W + (size_t)(n0 + row) * DMODEL + kt + col4);
        As[col4 + 0][row] = a4.x; As[col4 + 1][row] = a4.y;
        As[col4 + 2][row] = a4.z; As[col4 + 3][row] = a4.w;
        Bs[col4 + 0][row] = b4.x; Bs[col4 + 1][row] = b4.y;
        Bs[col4 + 2][row] = b4.z; Bs[col4 + 3][row] = b4.w;
        __syncthreads();
#pragma unroll
        for (int k = 0; k < 8; ++k) {
            float ar[8], br[8];
#pragma unroll
            for (int i = 0; i < 8; ++i) ar[i] = As[k][ty * 8 + i];
#pragma unroll
            for (int j = 0; j < 8; ++j) br[j] = Bs[k][tx * 8 + j];
#pragma unroll
            for (int i = 0; i < 8; ++i)
#pragma unroll
                for (int j = 0; j < 8; ++j) acc[i][j] += ar[i] * br[j];
        }
        __syncthreads();
    }

#pragma unroll
    for (int i = 0; i < 8; ++i) {
        int m  = m0 + ty * 8 + i;
        int b_ = m >> 11;
        int s_ = m & (SEQ - 1);
#pragma unroll
        for (int j = 0; j < 8; ++j) {
            int n = n0 + tx * 8 + j;
            int h = n >> 6, e = n & 63;
            float r = acc[i][j] + bias[n];
            __nv_bfloat16 hh = __float2bfloat16(r);
            __nv_bfloat16 ll = __float2bfloat16(r - __bfloat162float(hh));
            size_t o;
            if (z < 2)
                o = (((size_t)(b_ * NHEADS + h)) * SEQ + s_) * HEADDIM + e;
            else
                o = (((size_t)(b_ * NHEADS + h)) * HEADDIM + e) * SEQ + s_;
            dh[o] = hh; dl[o] = ll;
        }
    }
}

// ---------------- Output projection (fp32) -----------------------------------
__global__ __launch_bounds__(256) void oproj_kernel(
    const float* __restrict__ Wo, const float* __restrict__ bo,
    float* __restrict__ y)
{
    __shared__ float As[8][128];
    __shared__ float Bs[8][128];

    const int tid  = threadIdx.x;
    const int row  = tid >> 1;
    const int col4 = (tid & 1) * 4;
    const int m0   = blockIdx.y * 128;
    const int n0   = blockIdx.x * 128;
    const int ty   = tid >> 4;
    const int tx   = tid & 15;

    float acc[8][8];
#pragma unroll
    for (int i = 0; i < 8; ++i)
#pragma unroll
        for (int j = 0; j < 8; ++j) acc[i][j] = 0.f;

    for (int kt = 0; kt < DMODEL; kt += 8) {
        float4 a4 = *(const float4*)(g_O + (size_t)(m0 + row) * DMODEL + kt + col4);
        float4 b4 = *(const float4*)(Wo  + (size_t)(n0 + row) * DMODEL + kt + col4);
        As[col4 + 0][row] = a4.x; As[col4 + 1][row] = a4.y;
        As[col4 + 2][row] = a4.z; As[col4 + 3][row] = a4.w;
        Bs[col4 + 0][row] = b4.x; Bs[col4 + 1][row] = b4.y;
        Bs[col4 + 2][row] = b4.z; Bs[col4 + 3][row] = b4.w;
        __syncthreads();
#pragma unroll
        for (int k = 0; k < 8; ++k) {
            float ar[8], br[8];
#pragma unroll
            for (int i = 0; i < 8; ++i) ar[i] = As[k][ty * 8 + i];
#pragma unroll
            for (int j = 0; j < 8; ++j) br[j] = Bs[k][tx * 8 + j];
#pragma unroll
            for (int i = 0; i < 8; ++i)
#pragma unroll
                for (int j = 0; j < 8; ++j) acc[i][j] += ar[i] * br[j];
        }
        __syncthreads();
    }

#pragma unroll
    for (int i = 0; i < 8; ++i) {
        int m = m0 + ty * 8 + i;
#pragma unroll
        for (int j = 0; j < 8; ++j) {
            int n = n0 + tx * 8 + j;
            y[(size_t)m * DMODEL + n] = acc[i][j] + bo[n];
        }
    }
}

// ---------------- top-k helpers ----------------------------------------------
__device__ __forceinline__ uint32_t f2key(float f) {
    uint32_t u = __float_as_uint(f);
    return (u & 0x80000000u) ? ~u : (u | 0x80000000u);
}

__device__ uint32_t warp_kth_key(const float* __restrict__ row, int k,
                                 uint32_t* __restrict__ hist, int lane)
{
    uint32_t prefix = 0, mask_hi = 0;
    int want = k;
#pragma unroll
    for (int pass = 0; pass < 4; ++pass) {
        const int shift = 24 - pass * 8;
        for (int i = lane; i < 256; i += 32) hist[i] = 0;
        __syncwarp();
        for (int i = lane; i < SEQ; i += 32) {
            uint32_t key = f2key(row[i]);
            bool act = (((key ^ prefix) & mask_hi) == 0u);
            unsigned bal = __ballot_sync(0xffffffffu, act);
            if (act) {
                int bin = (key >> shift) & 0xFF;
                unsigned peers = __match_any_sync(bal, bin);
                if ((int)__ffs(peers) - 1 == lane)
                    atomicAdd(&hist[bin], (uint32_t)__popc(peers));
            }
        }
        __syncwarp();
        int c[8]; int lsum = 0;
#pragma unroll
        for (int i = 0; i < 8; ++i) { c[i] = (int)hist[lane * 8 + i]; lsum += c[i]; }
        int incl = lsum;
#pragma unroll
        for (int off = 1; off < 32; off <<= 1) {
            int t = __shfl_up_sync(0xffffffffu, incl, off);
            if (lane >= off) incl += t;
        }
        int total = __shfl_sync(0xffffffffu, incl, 31);
        int run = total - incl;
        int fd = -1, fw = 0;
#pragma unroll
        for (int i = 7; i >= 0; --i) {
            if (run < want && run + c[i] >= want) { fd = lane * 8 + i; fw = want - run; }
            run += c[i];
        }
        unsigned bal2 = __ballot_sync(0xffffffffu, fd >= 0);
        int src = __ffs(bal2) - 1;
        fd   = __shfl_sync(0xffffffffu, fd, src);
        want = __shfl_sync(0xffffffffu, fw, src);
        prefix  |= (uint32_t)fd << shift;
        mask_hi |= 0xFFu << shift;
        __syncwarp();
    }
    return prefix;
}

// ---------------- attention (warp-mma bf16x3) ---------------------------------
// dynamic smem (u32 view):
//  phase1: QH 0 (4608) | QL 4608 | KH 9216 | KL 13824   (each 128 rows * 36 u32)
//  phase2: rowbuf (float) w*2048, hist u32 at byte 131072 + w*1024
//  phase3: PH 0 (8704 = 128*68) | PL 8704 | VH 17408 (64*68) | VL 21760
#define DYN_BYTES 147456

__global__ __launch_bounds__(ATHREADS) void attn_kernel()
{
    extern __shared__ __align__(16) uint32_t sm32[];

    __shared__ uint32_t s_thr[TQ];
    __shared__ float    s_mx[TQ], s_inv[TQ];

    const int tid   = threadIdx.x;
    const int lane  = tid & 31, w = tid >> 5;
    const int group = lane >> 2, qd = lane & 3;
    const int wm    = w & 7;          // M-tile: rows [wm*16, +16)
    const int wn    = w >> 3;         // N-half
    const int qt    = blockIdx.x & (NQT - 1);
    const int bh    = blockIdx.x >> 4;
    const int qrow0 = qt * TQ;

    const size_t hb = (size_t)bh * SEQ * HEADDIM;
    const uint32_t* qh32 = (const uint32_t*)(g_Qh + hb) + (size_t)qrow0 * 32;
    const uint32_t* ql32 = (const uint32_t*)(g_Ql + hb) + (size_t)qrow0 * 32;
    const uint32_t* kh32 = (const uint32_t*)(g_Kh + hb);
    const uint32_t* kl32 = (const uint32_t*)(g_Kl + hb);
    const uint32_t* vh32 = (const uint32_t*)(g_Vth + hb);
    const uint32_t* vl32 = (const uint32_t*)(g_Vtl + hb);
    float* Sp = g_S + (size_t)blockIdx.x * TQ * SEQ;

    // ================= phase 1: S = Q@K^T * 0.125 -> g_S ====================
    {
        uint32_t* QH = sm32;
        uint32_t* QL = sm32 + 4608;
        uint32_t* KH = sm32 + 9216;
        uint32_t* KL = sm32 + 13824;

#pragma unroll
        for (int it = 0; it < 8; ++it) {
            int idx = tid + it * ATHREADS;          // 4096
            int r = idx >> 5, c = idx & 31;
            QH[r * 36 + c] = qh32[(size_t)r * 32 + c];
            QL[r * 36 + c] = ql32[(size_t)r * 32 + c];
        }

        for (int blk = 0; blk < 16; ++blk) {
            const int j0 = blk * 128;
            __syncthreads();
#pragma unroll
            for (int it = 0; it < 8; ++it) {
                int idx = tid + it * ATHREADS;
                int r = idx >> 5, c = idx & 31;
                KH[r * 36 + c] = kh32[(size_t)(j0 + r) * 32 + c];
                KL[r * 36 + c] = kl32[(size_t)(j0 + r) * 32 + c];
            }
            __syncthreads();

            float c8[8][4];
#pragma unroll
            for (int nt = 0; nt < 8; ++nt)
#pragma unroll
                for (int i = 0; i < 4; ++i) c8[nt][i] = 0.f;

            const int r0 = wm * 16 + group;
#pragma unroll
            for (int ks = 0; ks < 4; ++ks) {
                uint32_t ah[4], al[4];
                int cb = ks * 8 + qd;
                ah[0] = QH[r0 * 36 + cb];       ah[1] = QH[(r0 + 8) * 36 + cb];
                ah[2] = QH[r0 * 36 + cb + 4];   ah[3] = QH[(r0 + 8) * 36 + cb + 4];
                al[0] = QL[r0 * 36 + cb];       al[1] = QL[(r0 + 8) * 36 + cb];
                al[2] = QL[r0 * 36 + cb + 4];   al[3] = QL[(r0 + 8) * 36 + cb + 4];
#pragma unroll
                for (int nt = 0; nt < 8; ++nt) {
                    int kb = wn * 64 + nt * 8 + group;
                    uint32_t bhv[2], blv[2];
                    bhv[0] = KH[kb * 36 + cb]; bhv[1] = KH[kb * 36 + cb + 4];
                    blv[0] = KL[kb * 36 + cb]; blv[1] = KL[kb * 36 + cb + 4];
                    MMA16816(c8[nt], ah, bhv);
                    MMA16816(c8[nt], ah, blv);
                    MMA16816(c8[nt], al, bhv);
                }
            }
#pragma unroll
            for (int nt = 0; nt < 8; ++nt) {
                int col = j0 + wn * 64 + nt * 8 + qd * 2;
                float2 v0 = { c8[nt][0] * 0.125f, c8[nt][1] * 0.125f };
                float2 v1 = { c8[nt][2] * 0.125f, c8[nt][3] * 0.125f };
                *(float2*)(Sp + (size_t)r0 * SEQ + col)       = v0;
                *(float2*)(Sp + (size_t)(r0 + 8) * SEQ + col) = v1;
            }
        }
    }
    __syncthreads();

    // ================= phase 2: per-row (thr, mx, inv) ======================
    {
        float* rowbuf = (float*)sm32 + w * 2048;
        uint32_t* hist = (uint32_t*)((char*)sm32 + 131072) + w * 256;
        for (int t = 0; t < 8; ++t) {
            int r = w * 8 + t;
            const float* grow = Sp + (size_t)r * SEQ;
            float mx = -3.4e38f;
            for (int it = 0; it < 16; ++it) {
                float4 v = ((const float4*)grow)[lane + it * 32];
                ((float4*)rowbuf)[lane + it * 32] = v;
                mx = fmaxf(mx, fmaxf(fmaxf(v.x, v.y), fmaxf(v.z, v.w)));
            }
#pragma unroll
            for (int off = 16; off; off >>= 1)
                mx = fmaxf(mx, __shfl_xor_sync(0xffffffffu, mx, off));
            __syncwarp();
            uint32_t thr = warp_kth_key(rowbuf, KKEEP, hist, lane);
            float sum = 0.f;
            for (int i = lane; i < SEQ; i += 32) {
                float s = rowbuf[i];
                if (f2key(s) >= thr) sum += __expf(s - mx);
            }
#pragma unroll
            for (int off = 16; off; off >>= 1)
                sum += __shfl_xor_sync(0xffffffffu, sum, off);
            if (lane == 0) { s_thr[r] = thr; s_mx[r] = mx; s_inv[r] = 1.0f / sum; }
            __syncwarp();
        }
    }
    __syncthreads();

    // ================= phase 3: P (from g_S) @ V ===========================
    {
        uint32_t* PH = sm32;
        uint32_t* PL = sm32 + 8704;
        uint32_t* VH = sm32 + 17408;
        uint32_t* VL = sm32 + 21760;

        float c8[4][4];
#pragma unroll
        for (int nt = 0; nt < 4; ++nt)
#pragma unroll
            for (int i = 0; i < 4; ++i) c8[nt][i] = 0.f;

        const int pq  = tid >> 2;      // 0..127 (prob row for conversion)
        const int l4  = tid & 3;
        const int r0  = wm * 16 + group;

        for (int blk = 0; blk < 16; ++blk) {
            const int j0 = blk * 128;
            __syncthreads();
            // V tile: [64 e][64 u32]
#pragma unroll
            for (int it = 0; it < 8; ++it) {
                int idx = tid + it * ATHREADS;      // 4096
                int r = idx >> 6, c = idx & 63;
                VH[r * 68 + c] = vh32[(size_t)r * 1024 + (j0 >> 1) + c];
                VL[r * 68 + c] = vl32[(size_t)r * 1024 + (j0 >> 1) + c];
            }
            // P tile: read scores, mask+softmax, split hi/lo
            {
                uint32_t thr = s_thr[pq];
                float mx = s_mx[pq], inv = s_inv[pq];
                const float4* srow = (const float4*)(Sp + (size_t)pq * SEQ + j0);
#pragma unroll
                for (int it = 0; it < 8; ++it) {
                    float4 v = srow[l4 * 8 + it];
                    float p0 = (f2key(v.x) >= thr) ? __expf(v.x - mx) * inv : 0.f;
                    float p1 = (f2key(v.y) >= thr) ? __expf(v.y - mx) * inv : 0.f;
                    float p2 = (f2key(v.z) >= thr) ? __expf(v.z - mx) * inv : 0.f;
                    float p3 = (f2key(v.w) >= thr) ? __expf(v.w - mx) * inv : 0.f;
                    __nv_bfloat16 h0 = __float2bfloat16(p0), h1 = __float2bfloat16(p1);
                    __nv_bfloat16 h2 = __float2bfloat16(p2), h3 = __float2bfloat16(p3);
                    float l0 = p0 - __bfloat162float(h0), l1 = p1 - __bfloat162float(h1);
                    float l2 = p2 - __bfloat162float(h2), l3 = p3 - __bfloat162float(h3);
                    int cc = pq * 68 + l4 * 16 + it * 2;
                    PH[cc]     = ((uint32_t)__bfloat16_as_ushort(h1) << 16) | __bfloat16_as_ushort(h0);
                    PH[cc + 1] = ((uint32_t)__bfloat16_as_ushort(h3) << 16) | __bfloat16_as_ushort(h2);
                    PL[cc]     = ((uint32_t)__bfloat16_as_ushort(__float2bfloat16(l1)) << 16)
                               | __bfloat16_as_ushort(__float2bfloat16(l0));
                    PL[cc + 1] = ((uint32_t)__bfloat16_as_ushort(__float2bfloat16(l3)) << 16)
                               | __bfloat16_as_ushort(__float2bfloat16(l2));
                }
            }
            __syncthreads();

#pragma unroll
            for (int ks = 0; ks < 8; ++ks) {
                uint32_t ah[4], al[4];
                int cb = ks * 8 + qd;
                ah[0] = PH[r0 * 68 + cb];       ah[1] = PH[(r0 + 8) * 68 + cb];
                ah[2] = PH[r0 * 68 + cb + 4];   ah[3] = PH[(r0 + 8) * 68 + cb + 4];
                al[0] = PL[r0 * 68 + cb];       al[1] = PL[(r0 + 8) * 68 + cb];
                al[2] = PL[r0 * 68 + cb + 4];   al[3] = PL[(r0 + 8) * 68 + cb + 4];
#pragma unroll
                for (int nt = 0; nt < 4; ++nt) {
                    int eb = wn * 32 + nt * 8 + group;
                    uint32_t bhv[2], blv[2];
                    bhv[0] = VH[eb * 68 + cb]; bhv[1] = VH[eb * 68 + cb + 4];
                    blv[0] = VL[eb * 68 + cb]; blv[1] = VL[eb * 68 + cb + 4];
                    MMA16816(c8[nt], ah, bhv);
                    MMA16816(c8[nt], ah, blv);
                    MMA16816(c8[nt], al, bhv);
                }
            }
        }

        // final O epilogue
        const int b_ = bh / NHEADS, h = bh % NHEADS;
#pragma unroll
        for (int nt = 0; nt < 4; ++nt) {
            int e = h * HEADDIM + wn * 32 + nt * 8 + qd * 2;
            int s0 = qrow0 + r0, s1 = s0 + 8;
            float2 v0 = { c8[nt][0], c8[nt][1] };
            float2 v1 = { c8[nt][2], c8[nt][3] };
            *(float2*)(g_O + ((size_t)(b_ * SEQ + s0)) * DMODEL + e) = v0;
            *(float2*)(g_O + ((size_t)(b_ * SEQ + s1)) * DMODEL + e) = v1;
        }
    }
}

// ---------------- launch ------------------------------------------------------
extern "C" void kernel_launch(void* const* d_in, const int* in_sizes, int n_in,
                              void* d_out, int out_size)
{
    const float* x  = (const float*)d_in[0];
    const float* Wq = (const float*)d_in[1];
    const float* bq = (const float*)d_in[2];
    const float* Wk = (const float*)d_in[3];
    const float* bk = (const float*)d_in[4];
    const float* Wv = (const float*)d_in[5];
    const float* bv = (const float*)d_in[6];
    const float* Wo = (const float*)d_in[7];
    const float* bo = (const float*)d_in[8];
    float* y = (float*)d_out;

    dim3 g1(DMODEL / 128, (BATCH * SEQ) / 128, 3);
    qkv_kernel<<<g1, 256>>>(x, Wq, bq, Wk, bk, Wv, bv);

    cudaFuncSetAttribute(attn_kernel, cudaFuncAttributeMaxDynamicSharedMemorySize, DYN_BYTES);
    attn_kernel<<<BATCH * NHEADS * NQT, ATHREADS, DYN_BYTES>>>();

    dim3 g2(DMODEL / 128, (BATCH * SEQ) / 128);
    oproj_kernel<<<g2, 256>>>(Wo, bo, y);
}

// round 6
// speedup vs baseline: 1.5133x; 1.0641x over previous
#include <cuda_runtime.h>
#include <cuda_bf16.h>
#include <cstdint>

#define BATCH   2
#define SEQ     2048
#define DMODEL  768
#define NHEADS  12
#define HEADDIM 64
#define KKEEP   614
#define TQ      128
#define NQT     (SEQ / TQ)
#define ATHREADS 512

// ---------------- device scratch --------------------------------------------
__device__ __align__(16) __nv_bfloat16 g_Qh[BATCH * NHEADS * SEQ * HEADDIM];
__device__ __align__(16) __nv_bfloat16 g_Ql[BATCH * NHEADS * SEQ * HEADDIM];
__device__ __align__(16) __nv_bfloat16 g_Kh[BATCH * NHEADS * SEQ * HEADDIM];
__device__ __align__(16) __nv_bfloat16 g_Kl[BATCH * NHEADS * SEQ * HEADDIM];
__device__ __align__(16) __nv_bfloat16 g_Vth[BATCH * NHEADS * HEADDIM * SEQ];
__device__ __align__(16) __nv_bfloat16 g_Vtl[BATCH * NHEADS * HEADDIM * SEQ];
__device__ __align__(16) float g_O[BATCH * SEQ * DMODEL];
__device__ __align__(16) float g_S[(size_t)BATCH * NHEADS * SEQ * SEQ];

// m16n8k16 bf16 mma, fp32 accum
#define MMA16816(c, a, b)                                                        \
    asm volatile("mma.sync.aligned.m16n8k16.row.col.f32.bf16.bf16.f32 "          \
        "{%0,%1,%2,%3}, {%4,%5,%6,%7}, {%8,%9}, {%0,%1,%2,%3};"                  \
        : "+f"((c)[0]), "+f"((c)[1]), "+f"((c)[2]), "+f"((c)[3])                 \
        : "r"((a)[0]), "r"((a)[1]), "r"((a)[2]), "r"((a)[3]),                    \
          "r"((b)[0]), "r"((b)[1]))

static __device__ __forceinline__ uint32_t smem_u32(const void* p) {
    uint32_t a;
    asm("{ .reg .u64 t; cvta.to.shared.u64 t, %1; cvt.u32.u64 %0, t; }" : "=r"(a) : "l"(p));
    return a;
}
static __device__ __forceinline__ void cp16(uint32_t dst, const void* src) {
    asm volatile("cp.async.ca.shared.global [%0], [%1], 16;" :: "r"(dst), "l"(src));
}
#define CP_COMMIT() asm volatile("cp.async.commit_group;" ::: "memory")
#define CP_WAIT1()  asm volatile("cp.async.wait_group 1;" ::: "memory")
#define CP_WAIT0()  asm volatile("cp.async.wait_group 0;" ::: "memory")

// ---------------- QKV projection (fp32 GEMM, bf16 hi/lo epilogue) ------------
__global__ __launch_bounds__(256, 2) void qkv_kernel(
    const float* __restrict__ x,
    const float* __restrict__ Wq, const float* __restrict__ bq,
    const float* __restrict__ Wk, const float* __restrict__ bk,
    const float* __restrict__ Wv, const float* __restrict__ bv)
{
    const float* W; const float* bias;
    __nv_bfloat16 *dh, *dl;
    const int z = blockIdx.z;
    if (z == 0)      { W = Wq; bias = bq; dh = g_Qh;  dl = g_Ql;  }
    else if (z == 1) { W = Wk; bias = bk; dh = g_Kh;  dl = g_Kl;  }
    else             { W = Wv; bias = bv; dh = g_Vth; dl = g_Vtl; }

    __shared__ float As[8][128];
    __shared__ float Bs[8][128];

    const int tid  = threadIdx.x;
    const int row  = tid >> 1;
    const int col4 = (tid & 1) * 4;
    const int m0   = blockIdx.y * 128;
    const int n0   = blockIdx.x * 128;
    const int ty   = tid >> 4;
    const int tx   = tid & 15;

    float acc[8][8];
#pragma unroll
    for (int i = 0; i < 8; ++i)
#pragma unroll
        for (int j = 0; j < 8; ++j) acc[i][j] = 0.f;

    for (int kt = 0; kt < DMODEL; kt += 8) {
        float4 a4 = *(const float4*)(x + (size_t)(m0 + row) * DMODEL + kt + col4);
        float4 b4 = *(const float4*)(W + (size_t)(n0 + row) * DMODEL + kt + col4);
        As[col4 + 0][row] = a4.x; As[col4 + 1][row] = a4.y;
        As[col4 + 2][row] = a4.z; As[col4 + 3][row] = a4.w;
        Bs[col4 + 0][row] = b4.x; Bs[col4 + 1][row] = b4.y;
        Bs[col4 + 2][row] = b4.z; Bs[col4 + 3][row] = b4.w;
        __syncthreads();
#pragma unroll
        for (int k = 0; k < 8; ++k) {
            float ar[8], br[8];
#pragma unroll
            for (int i = 0; i < 8; ++i) ar[i] = As[k][ty * 8 + i];
#pragma unroll
            for (int j = 0; j < 8; ++j) br[j] = Bs[k][tx * 8 + j];
#pragma unroll
            for (int i = 0; i < 8; ++i)
#pragma unroll
                for (int j = 0; j < 8; ++j) acc[i][j] += ar[i] * br[j];
        }
        __syncthreads();
    }

#pragma unroll
    for (int i = 0; i < 8; ++i) {
        int m  = m0 + ty * 8 + i;
        int b_ = m >> 11;
        int s_ = m & (SEQ - 1);
#pragma unroll
        for (int j = 0; j < 8; ++j) {
            int n = n0 + tx * 8 + j;
            int h = n >> 6, e = n & 63;
            float r = acc[i][j] + bias[n];
            __nv_bfloat16 hh = __float2bfloat16(r);
            __nv_bfloat16 ll = __float2bfloat16(r - __bfloat162float(hh));
            size_t o;
            if (z < 2)
                o = (((size_t)(b_ * NHEADS + h)) * SEQ + s_) * HEADDIM + e;
            else
                o = (((size_t)(b_ * NHEADS + h)) * HEADDIM + e) * SEQ + s_;
            dh[o] = hh; dl[o] = ll;
        }
    }
}

// ---------------- Output projection (fp32) -----------------------------------
__global__ __launch_bounds__(256) void oproj_kernel(
    const float* __restrict__ Wo, const float* __restrict__ bo,
    float* __restrict__ y)
{
    __shared__ float As[8][128];
    __shared__ float Bs[8][128];

    const int tid  = threadIdx.x;
    const int row  = tid >> 1;
    const int col4 = (tid & 1) * 4;
    const int m0   = blockIdx.y * 128;
    const int n0   = blockIdx.x * 128;
    const int ty   = tid >> 4;
    const int tx   = tid & 15;

    float acc[8][8];
#pragma unroll
    for (int i = 0; i < 8; ++i)
#pragma unroll
        for (int j = 0; j < 8; ++j) acc[i][j] = 0.f;

    for (int kt = 0; kt < DMODEL; kt += 8) {
        float4 a4 = *(const float4*)(g_O + (size_t)(m0 + row) * DMODEL + kt + col4);
        float4 b4 = *(const float4*)(Wo  + (size_t)(n0 + row) * DMODEL + kt + col4);
        As[col4 + 0][row] = a4.x; As[col4 + 1][row] = a4.y;
        As[col4 + 2][row] = a4.z; As[col4 + 3][row] = a4.w;
        Bs[col4 + 0][row] = b4.x; Bs[col4 + 1][row] = b4.y;
        Bs[col4 + 2][row] = b4.z; Bs[col4 + 3][row] = b4.w;
        __syncthreads();
#pragma unroll
        for (int k = 0; k < 8; ++k) {
            float ar[8], br[8];
#pragma unroll
            for (int i = 0; i < 8; ++i) ar[i] = As[k][ty * 8 + i];
#pragma unroll
            for (int j = 0; j < 8; ++j) br[j] = Bs[k][tx * 8 + j];
#pragma unroll
            for (int i = 0; i < 8; ++i)
#pragma unroll
                for (int j = 0; j < 8; ++j) acc[i][j] += ar[i] * br[j];
        }
        __syncthreads();
    }

#pragma unroll
    for (int i = 0; i < 8; ++i) {
        int m = m0 + ty * 8 + i;
#pragma unroll
        for (int j = 0; j < 8; ++j) {
            int n = n0 + tx * 8 + j;
            y[(size_t)m * DMODEL + n] = acc[i][j] + bo[n];
        }
    }
}

// ---------------- top-k helpers ----------------------------------------------
__device__ __forceinline__ uint32_t f2key(float f) {
    uint32_t u = __float_as_uint(f);
    return (u & 0x80000000u) ? ~u : (u | 0x80000000u);
}

__device__ uint32_t warp_kth_key(const float* __restrict__ row, int k,
                                 uint32_t* __restrict__ hist, int lane)
{
    uint32_t prefix = 0, mask_hi = 0;
    int want = k;
#pragma unroll
    for (int pass = 0; pass < 4; ++pass) {
        const int shift = 24 - pass * 8;
        for (int i = lane; i < 256; i += 32) hist[i] = 0;
        __syncwarp();
        for (int i = lane; i < SEQ; i += 32) {
            uint32_t key = f2key(row[i]);
            bool act = (((key ^ prefix) & mask_hi) == 0u);
            unsigned bal = __ballot_sync(0xffffffffu, act);
            if (act) {
                int bin = (key >> shift) & 0xFF;
                unsigned peers = __match_any_sync(bal, bin);
                if ((int)__ffs(peers) - 1 == lane)
                    atomicAdd(&hist[bin], (uint32_t)__popc(peers));
            }
        }
        __syncwarp();
        int c[8]; int lsum = 0;
#pragma unroll
        for (int i = 0; i < 8; ++i) { c[i] = (int)hist[lane * 8 + i]; lsum += c[i]; }
        int incl = lsum;
#pragma unroll
        for (int off = 1; off < 32; off <<= 1) {
            int t = __shfl_up_sync(0xffffffffu, incl, off);
            if (lane >= off) incl += t;
        }
        int total = __shfl_sync(0xffffffffu, incl, 31);
        int run = total - incl;
        int fd = -1, fw = 0;
#pragma unroll
        for (int i = 7; i >= 0; --i) {
            if (run < want && run + c[i] >= want) { fd = lane * 8 + i; fw = want - run; }
            run += c[i];
        }
        unsigned bal2 = __ballot_sync(0xffffffffu, fd >= 0);
        int src = __ffs(bal2) - 1;
        fd   = __shfl_sync(0xffffffffu, fd, src);
        want = __shfl_sync(0xffffffffu, fw, src);
        prefix  |= (uint32_t)fd << shift;
        mask_hi |= 0xFFu << shift;
        __syncwarp();
    }
    return prefix;
}

// ---------------- attention (warp-mma bf16x3 + cp.async pipeline) -------------
// smem (u32):
//  ph1: QH 0 (4608) | QL 4608 | Kbuf[2] at 9216 + b*9216 (KH +0, KL +4608)  -> 27648
//  ph2: rowbuf w*2048 floats (0..32768) | hist 32768 + w*256                -> 36864
//  ph3: PH 0 (8704) | PL 8704 | Vbuf[2] at 17408 + b*8704 (VH +0, VL +4352) -> 34816
#define DYN_BYTES 147456

__global__ __launch_bounds__(ATHREADS) void attn_kernel()
{
    extern __shared__ __align__(16) uint32_t sm32[];

    __shared__ uint32_t s_thr[TQ];
    __shared__ float    s_mx[TQ], s_inv[TQ];

    const int tid   = threadIdx.x;
    const int lane  = tid & 31, w = tid >> 5;
    const int group = lane >> 2, qd = lane & 3;
    const int wm    = w & 7;
    const int wn    = w >> 3;
    const int qt    = blockIdx.x & (NQT - 1);
    const int bh    = blockIdx.x >> 4;
    const int qrow0 = qt * TQ;

    const size_t hb = (size_t)bh * SEQ * HEADDIM;
    const uint32_t* qh32 = (const uint32_t*)(g_Qh + hb) + (size_t)qrow0 * 32;
    const uint32_t* ql32 = (const uint32_t*)(g_Ql + hb) + (size_t)qrow0 * 32;
    const uint32_t* kh32 = (const uint32_t*)(g_Kh + hb);
    const uint32_t* kl32 = (const uint32_t*)(g_Kl + hb);
    const uint32_t* vh32 = (const uint32_t*)(g_Vth + hb);
    const uint32_t* vl32 = (const uint32_t*)(g_Vtl + hb);
    float* Sp = g_S + (size_t)blockIdx.x * TQ * SEQ;

    const uint32_t smb = smem_u32(sm32);

    // ================= phase 1: S = Q@K^T * 0.125 -> g_S ====================
    {
        uint32_t* QH = sm32;
        uint32_t* QL = sm32 + 4608;

#pragma unroll
        for (int it = 0; it < 8; ++it) {
            int idx = tid + it * ATHREADS;
            int r = idx >> 5, c = idx & 31;
            QH[r * 36 + c] = qh32[(size_t)r * 32 + c];
            QL[r * 36 + c] = ql32[(size_t)r * 32 + c];
        }

        // async K tile loader: 128 rows x 8 chunks x {H,L} = 2048 cp16
        auto loadK = [&](int blk, int buf) {
            const int j0 = blk * 128;
            const uint32_t dstb = smb + (9216 + buf * 9216) * 4;
#pragma unroll
            for (int it = 0; it < 4; ++it) {
                int idx = tid + it * ATHREADS;          // 0..2047
                int arr = idx >> 10, rem = idx & 1023;
                int r = rem >> 3, ch = rem & 7;
                uint32_t dst = dstb + (arr * 4608 + r * 36 + ch * 4) * 4;
                const uint32_t* src = (arr ? kl32 : kh32) + (size_t)(j0 + r) * 32 + ch * 4;
                cp16(dst, src);
            }
        };

        loadK(0, 0); CP_COMMIT();

        for (int blk = 0; blk < 16; ++blk) {
            __syncthreads();                 // all warps done with prev compute
            if (blk + 1 < 16) { loadK(blk + 1, (blk + 1) & 1); CP_COMMIT(); CP_WAIT1(); }
            else              { CP_WAIT0(); }
            __syncthreads();

            const uint32_t* KH = sm32 + 9216 + (blk & 1) * 9216;
            const uint32_t* KL = KH + 4608;
            const int j0 = blk * 128;

            float c8[8][4];
#pragma unroll
            for (int nt = 0; nt < 8; ++nt)
#pragma unroll
                for (int i = 0; i < 4; ++i) c8[nt][i] = 0.f;

            const int r0 = wm * 16 + group;
#pragma unroll
            for (int ks = 0; ks < 4; ++ks) {
                uint32_t ah[4], al[4];
                int cb = ks * 8 + qd;
                ah[0] = QH[r0 * 36 + cb];       ah[1] = QH[(r0 + 8) * 36 + cb];
                ah[2] = QH[r0 * 36 + cb + 4];   ah[3] = QH[(r0 + 8) * 36 + cb + 4];
                al[0] = QL[r0 * 36 + cb];       al[1] = QL[(r0 + 8) * 36 + cb];
                al[2] = QL[r0 * 36 + cb + 4];   al[3] = QL[(r0 + 8) * 36 + cb + 4];
#pragma unroll
                for (int nt = 0; nt < 8; ++nt) {
                    int kb = wn * 64 + nt * 8 + group;
                    uint32_t bhv[2], blv[2];
                    bhv[0] = KH[kb * 36 + cb]; bhv[1] = KH[kb * 36 + cb + 4];
                    blv[0] = KL[kb * 36 + cb]; blv[1] = KL[kb * 36 + cb + 4];
                    MMA16816(c8[nt], ah, bhv);
                    MMA16816(c8[nt], ah, blv);
                    MMA16816(c8[nt], al, bhv);
                }
            }
#pragma unroll
            for (int nt = 0; nt < 8; ++nt) {
                int col = j0 + wn * 64 + nt * 8 + qd * 2;
                float2 v0 = { c8[nt][0] * 0.125f, c8[nt][1] * 0.125f };
                float2 v1 = { c8[nt][2] * 0.125f, c8[nt][3] * 0.125f };
                *(float2*)(Sp + (size_t)r0 * SEQ + col)       = v0;
                *(float2*)(Sp + (size_t)(r0 + 8) * SEQ + col) = v1;
            }
        }
    }
    __syncthreads();

    // ================= phase 2: per-row (thr, mx, inv) ======================
    {
        float* rowbuf = (float*)sm32 + w * 2048;
        uint32_t* hist = sm32 + 32768 + w * 256;
        for (int t = 0; t < 8; ++t) {
            int r = w * 8 + t;
            const float* grow = Sp + (size_t)r * SEQ;
            float mx = -3.4e38f;
            for (int it = 0; it < 16; ++it) {
                float4 v = ((const float4*)grow)[lane + it * 32];
                ((float4*)rowbuf)[lane + it * 32] = v;
                mx = fmaxf(mx, fmaxf(fmaxf(v.x, v.y), fmaxf(v.z, v.w)));
            }
#pragma unroll
            for (int off = 16; off; off >>= 1)
                mx = fmaxf(mx, __shfl_xor_sync(0xffffffffu, mx, off));
            __syncwarp();
            uint32_t thr = warp_kth_key(rowbuf, KKEEP, hist, lane);
            float sum = 0.f;
            for (int i = lane; i < SEQ; i += 32) {
                float s = rowbuf[i];
                if (f2key(s) >= thr) sum += __expf(s - mx);
            }
#pragma unroll
            for (int off = 16; off; off >>= 1)
                sum += __shfl_xor_sync(0xffffffffu, sum, off);
            if (lane == 0) { s_thr[r] = thr; s_mx[r] = mx; s_inv[r] = 1.0f / sum; }
            __syncwarp();
        }
    }
    __syncthreads();

    // ================= phase 3: P (from g_S) @ V ===========================
    {
        uint32_t* PH = sm32;
        uint32_t* PL = sm32 + 8704;

        // async V tile loader: 64 rows x 16 chunks x {H,L} = 2048 cp16
        auto loadV = [&](int blk, int buf) {
            const int j0 = blk * 128;
            const uint32_t dstb = smb + (17408 + buf * 8704) * 4;
#pragma unroll
            for (int it = 0; it < 4; ++it) {
                int idx = tid + it * ATHREADS;
                int arr = idx >> 10, rem = idx & 1023;
                int r = rem >> 4, ch = rem & 15;
                uint32_t dst = dstb + (arr * 4352 + r * 68 + ch * 4) * 4;
                const uint32_t* src = (arr ? vl32 : vh32) + (size_t)r * 1024 + (j0 >> 1) + ch * 4;
                cp16(dst, src);
            }
        };

        float c8[4][4];
#pragma unroll
        for (int nt = 0; nt < 4; ++nt)
#pragma unroll
            for (int i = 0; i < 4; ++i) c8[nt][i] = 0.f;

        const int pq  = tid >> 2;
        const int l4  = tid & 3;
        const int r0  = wm * 16 + group;

        loadV(0, 0); CP_COMMIT();

        for (int blk = 0; blk < 16; ++blk) {
            const int j0 = blk * 128;
            __syncthreads();                 // done reading PH/PL + V of prev blk
            if (blk + 1 < 16) { loadV(blk + 1, (blk + 1) & 1); CP_COMMIT(); }
            // P conversion overlaps in-flight V loads
            {
                uint32_t thr = s_thr[pq];
                float mx = s_mx[pq], inv = s_inv[pq];
                const float4* srow = (const float4*)(Sp + (size_t)pq * SEQ + j0);
#pragma unroll
                for (int it = 0; it < 8; ++it) {
                    float4 v = srow[l4 * 8 + it];
                    float p0 = (f2key(v.x) >= thr) ? __expf(v.x - mx) * inv : 0.f;
                    float p1 = (f2key(v.y) >= thr) ? __expf(v.y - mx) * inv : 0.f;
                    float p2 = (f2key(v.z) >= thr) ? __expf(v.z - mx) * inv : 0.f;
                    float p3 = (f2key(v.w) >= thr) ? __expf(v.w - mx) * inv : 0.f;
                    __nv_bfloat16 h0 = __float2bfloat16(p0), h1 = __float2bfloat16(p1);
                    __nv_bfloat16 h2 = __float2bfloat16(p2), h3 = __float2bfloat16(p3);
                    float l0 = p0 - __bfloat162float(h0), l1 = p1 - __bfloat162float(h1);
                    float l2 = p2 - __bfloat162float(h2), l3 = p3 - __bfloat162float(h3);
                    int cc = pq * 68 + l4 * 16 + it * 2;
                    PH[cc]     = ((uint32_t)__bfloat16_as_ushort(h1) << 16) | __bfloat16_as_ushort(h0);
                    PH[cc + 1] = ((uint32_t)__bfloat16_as_ushort(h3) << 16) | __bfloat16_as_ushort(h2);
                    PL[cc]     = ((uint32_t)__bfloat16_as_ushort(__float2bfloat16(l1)) << 16)
                               | __bfloat16_as_ushort(__float2bfloat16(l0));
                    PL[cc + 1] = ((uint32_t)__bfloat16_as_ushort(__float2bfloat16(l3)) << 16)
                               | __bfloat16_as_ushort(__float2bfloat16(l2));
                }
            }
            if (blk + 1 < 16) CP_WAIT1(); else CP_WAIT0();
            __syncthreads();

            const uint32_t* VH = sm32 + 17408 + (blk & 1) * 8704;
            const uint32_t* VL = VH + 4352;

#pragma unroll
            for (int ks = 0; ks < 8; ++ks) {
                uint32_t ah[4], al[4];
                int cb = ks * 8 + qd;
                ah[0] = PH[r0 * 68 + cb];       ah[1] = PH[(r0 + 8) * 68 + cb];
                ah[2] = PH[r0 * 68 + cb + 4];   ah[3] = PH[(r0 + 8) * 68 + cb + 4];
                al[0] = PL[r0 * 68 + cb];       al[1] = PL[(r0 + 8) * 68 + cb];
                al[2] = PL[r0 * 68 + cb + 4];   al[3] = PL[(r0 + 8) * 68 + cb + 4];
#pragma unroll
                for (int nt = 0; nt < 4; ++nt) {
                    int eb = wn * 32 + nt * 8 + group;
                    uint32_t bhv[2], blv[2];
                    bhv[0] = VH[eb * 68 + cb]; bhv[1] = VH[eb * 68 + cb + 4];
                    blv[0] = VL[eb * 68 + cb]; blv[1] = VL[eb * 68 + cb + 4];
                    MMA16816(c8[nt], ah, bhv);
                    MMA16816(c8[nt], ah, blv);
                    MMA16816(c8[nt], al, bhv);
                }
            }
        }

        const int b_ = bh / NHEADS, h = bh % NHEADS;
#pragma unroll
        for (int nt = 0; nt < 4; ++nt) {
            int e = h * HEADDIM + wn * 32 + nt * 8 + qd * 2;
            int s0 = qrow0 + r0, s1 = s0 + 8;
            float2 v0 = { c8[nt][0], c8[nt][1] };
            float2 v1 = { c8[nt][2], c8[nt][3] };
            *(float2*)(g_O + ((size_t)(b_ * SEQ + s0)) * DMODEL + e) = v0;
            *(float2*)(g_O + ((size_t)(b_ * SEQ + s1)) * DMODEL + e) = v1;
        }
    }
}

// ---------------- launch ------------------------------------------------------
extern "C" void kernel_launch(void* const* d_in, const int* in_sizes, int n_in,
                              void* d_out, int out_size)
{
    const float* x  = (const float*)d_in[0];
    const float* Wq = (const float*)d_in[1];
    const float* bq = (const float*)d_in[2];
    const float* Wk = (const float*)d_in[3];
    const float* bk = (const float*)d_in[4];
    const float* Wv = (const float*)d_in[5];
    const float* bv = (const float*)d_in[6];
    const float* Wo = (const float*)d_in[7];
    const float* bo = (const float*)d_in[8];
    float* y = (float*)d_out;

    dim3 g1(DMODEL / 128, (BATCH * SEQ) / 128, 3);
    qkv_kernel<<<g1, 256>>>(x, Wq, bq, Wk, bk, Wv, bv);

    cudaFuncSetAttribute(attn_kernel, cudaFuncAttributeMaxDynamicSharedMemorySize, DYN_BYTES);
    attn_kernel<<<BATCH * NHEADS * NQT, ATHREADS, DYN_BYTES>>>();

    dim3 g2(DMODEL / 128, (BATCH * SEQ) / 128);
    oproj_kernel<<<g2, 256>>>(Wo, bo, y);
}